// round 5
// baseline (speedup 1.0000x reference)
#include <cuda_runtime.h>
#include <cuda_bf16.h>
#include <cstdint>

// ---------------------------------------------------------------------------
// GCN (3-layer) on GB300.
//   per layer: xw = H @ W ; xw_scaled = xw * dinv[row]
//              acc[c] = xw_scaled[c] (self loop) + sum_{edges r->c} xw_scaled[r]
//              out[c] = acc[c] * dinv[c] + b ; relu (layers 1,2)
// Edge index dtype (int32 vs int64) auto-detected on device.
// ---------------------------------------------------------------------------

#define N_MAX 100000
#define D_H   64

static __device__ __align__(256) float g_bufA[(size_t)N_MAX * D_H];   // xw_scaled
static __device__ __align__(256) float g_bufB[(size_t)N_MAX * D_H];   // acc
static __device__ __align__(256) float g_bufC[(size_t)N_MAX * D_H];   // h
static __device__ __align__(256) float g_deg[N_MAX];                  // deg -> dinv
static __device__ int g_mode;  // 0 = int64 indices, 1 = int32 indices

// ---------------- dtype detection ----------------
// int32 data read as int64 packs two ids -> value >= n almost surely.
__global__ void detect_mode_kernel(const void* ei, int E, int n) {
    __shared__ int bad;
    if (threadIdx.x == 0) bad = 0;
    __syncthreads();
    const long long* p = (const long long*)ei;
    int cnt = min(E, 1024);
    for (int i = threadIdx.x; i < cnt; i += blockDim.x) {
        unsigned long long v = (unsigned long long)p[i];
        if (v >= (unsigned long long)n) atomicOr(&bad, 1);
    }
    __syncthreads();
    if (threadIdx.x == 0) g_mode = bad ? 1 : 0;
}

__device__ __forceinline__ int edge_idx(const void* ei, long long pos, int mode) {
    return mode ? ((const int*)ei)[pos] : (int)((const long long*)ei)[pos];
}

// ---------------- degree / dinv ----------------

__global__ void init_deg_kernel(float* deg, int n) {
    int i = blockIdx.x * blockDim.x + threadIdx.x;
    if (i < n) deg[i] = 1.0f;  // self loop
}

__global__ void deg_accum_kernel(float* deg, const void* ei, int E, int n) {
    int e = blockIdx.x * blockDim.x + threadIdx.x;
    if (e < E) {
        int mode = g_mode;
        unsigned c = (unsigned)edge_idx(ei, (long long)E + e, mode);  // col
        if (c < (unsigned)n) atomicAdd(&deg[c], 1.0f);
    }
}

__global__ void dinv_kernel(float* deg, int n) {
    int i = blockIdx.x * blockDim.x + threadIdx.x;
    if (i < n) deg[i] = rsqrtf(deg[i]);
}

// ---------------- GEMM + dinv[row] scale, dual-write ----------------

template <int DIN, int DOUT>
__global__ void gemm_scale_kernel(const float* __restrict__ X,
                                  const float* __restrict__ W,
                                  const float* __restrict__ dinv,
                                  float* __restrict__ xw,
                                  float* __restrict__ acc,
                                  int M) {
    constexpr int KT = 16;
    __shared__ __align__(16) float Ws[DIN * DOUT];
    __shared__ float Xs[128 * (KT + 1)];   // stride 17 -> conflict-free LDS

    const int tid = threadIdx.x;           // 0..127
    const int row0 = blockIdx.x * 128;
    const int row = row0 + tid;

    for (int i = tid; i < DIN * DOUT; i += 128) Ws[i] = W[i];

    float a[DOUT];
#pragma unroll
    for (int j = 0; j < DOUT; j++) a[j] = 0.0f;

    for (int k0 = 0; k0 < DIN; k0 += KT) {
        __syncthreads();
        for (int f = tid; f < 128 * (KT / 4); f += 128) {
            int r = f >> 2;           // tile row
            int c = (f & 3) * 4;      // float offset within KT
            int gr = row0 + r;
            float4 v = make_float4(0.f, 0.f, 0.f, 0.f);
            if (gr < M) v = *(const float4*)&X[(size_t)gr * DIN + k0 + c];
            float* dst = &Xs[r * (KT + 1) + c];
            dst[0] = v.x; dst[1] = v.y; dst[2] = v.z; dst[3] = v.w;
        }
        __syncthreads();
#pragma unroll
        for (int k = 0; k < KT; k++) {
            float xv = Xs[tid * (KT + 1) + k];
            const float* wrow = &Ws[(k0 + k) * DOUT];
#pragma unroll
            for (int j = 0; j < DOUT; j += 4) {
                float4 w = *(const float4*)&wrow[j];
                a[j + 0] += xv * w.x;
                a[j + 1] += xv * w.y;
                a[j + 2] += xv * w.z;
                a[j + 3] += xv * w.w;
            }
        }
    }

    if (row < M) {
        float s = dinv[row];
#pragma unroll
        for (int j = 0; j < DOUT; j += 4) {
            float4 v = make_float4(a[j] * s, a[j + 1] * s, a[j + 2] * s, a[j + 3] * s);
            *(float4*)&xw[(size_t)row * DOUT + j] = v;
            *(float4*)&acc[(size_t)row * DOUT + j] = v;
        }
    }
}

// ---------------- edge scatter: acc[col] += xw_scaled[row] ----------------
// One thread per (edge, float4-chunk); vector RED cuts L2 atomic ops 4x.

template <int D>
__global__ void scatter_kernel(const float* __restrict__ xw,
                               float* __restrict__ acc,
                               const void* __restrict__ ei,
                               int E, int n) {
    constexpr int C = D / 4;
    int i = blockIdx.x * blockDim.x + threadIdx.x;
    if (i >= E * C) return;
    int e = i / C;
    int c = i - e * C;
    int mode = g_mode;
    unsigned r  = (unsigned)edge_idx(ei, e, mode);                   // row
    unsigned cc = (unsigned)edge_idx(ei, (long long)E + e, mode);    // col
    if (r >= (unsigned)n || cc >= (unsigned)n) return;   // defensive
    float4 v = __ldg((const float4*)(xw + (size_t)r * D) + c);
    float* dst = acc + (size_t)cc * D + c * 4;
    asm volatile("red.global.add.v4.f32 [%0], {%1,%2,%3,%4};"
                 :: "l"(dst), "f"(v.x), "f"(v.y), "f"(v.z), "f"(v.w)
                 : "memory");
}

// ---------------- epilogue: out = acc * dinv[col] + b (opt. relu) ----------------

template <int D, bool RELU>
__global__ void epilogue_kernel(const float* __restrict__ acc,
                                const float* __restrict__ dinv,
                                const float* __restrict__ b,
                                float* __restrict__ out,
                                int M) {
    constexpr int C = D / 4;
    int i = blockIdx.x * blockDim.x + threadIdx.x;
    if (i >= M * C) return;
    int r = i / C;
    int c = i - r * C;
    float s = dinv[r];
    float4 v = __ldg((const float4*)acc + i);
    float4 bb = __ldg((const float4*)b + c);
    float4 o;
    o.x = v.x * s + bb.x;
    o.y = v.y * s + bb.y;
    o.z = v.z * s + bb.z;
    o.w = v.w * s + bb.w;
    if (RELU) {
        o.x = fmaxf(o.x, 0.f); o.y = fmaxf(o.y, 0.f);
        o.z = fmaxf(o.z, 0.f); o.w = fmaxf(o.w, 0.f);
    }
    ((float4*)out)[i] = o;
}

// ---------------- launch ----------------

extern "C" void kernel_launch(void* const* d_in, const int* in_sizes, int n_in,
                              void* d_out, int out_size) {
    // Identify inputs by element count (robust to metadata ordering).
    int i_x = -1, i_ei = -1, i_w1 = -1, i_w2 = -1, i_w3 = -1;
    int i_b1 = -1, i_b2 = -1, i_b3 = -1;
    for (int i = 0; i < n_in; i++) {
        int s = in_sizes[i];
        if      (s == 12800000) i_x  = i;
        else if (s == 3200000)  i_ei = i;
        else if (s == 8192)     i_w1 = i;
        else if (s == 4096)     i_w2 = i;
        else if (s == 2560)     i_w3 = i;
        else if (s == 40)       i_b3 = i;
        else if (s == 64)       { if (i_b1 < 0) i_b1 = i; else i_b2 = i; }
    }
    if (i_x < 0 || i_ei < 0 || i_w1 < 0 || i_b1 < 0 || i_w2 < 0 ||
        i_b2 < 0 || i_w3 < 0 || i_b3 < 0) {
        i_x = 0; i_ei = 1; i_w1 = 2; i_b1 = 3; i_w2 = 4; i_b2 = 5; i_w3 = 6; i_b3 = 7;
    }

    const float* x  = (const float*)d_in[i_x];
    const void*  ei = d_in[i_ei];
    const float* W1 = (const float*)d_in[i_w1];
    const float* b1 = (const float*)d_in[i_b1];
    const float* W2 = (const float*)d_in[i_w2];
    const float* b2 = (const float*)d_in[i_b2];
    const float* W3 = (const float*)d_in[i_w3];
    const float* b3 = (const float*)d_in[i_b3];

    const int M = in_sizes[i_x] / 128;     // 100000
    const int E = in_sizes[i_ei] / 2;      // 1600000
    float* out = (float*)d_out;

    float *pA, *pB, *pC, *pDeg;
    cudaGetSymbolAddress((void**)&pA, g_bufA);
    cudaGetSymbolAddress((void**)&pB, g_bufB);
    cudaGetSymbolAddress((void**)&pC, g_bufC);
    cudaGetSymbolAddress((void**)&pDeg, g_deg);

    const int T = 256;
    detect_mode_kernel<<<1, 256>>>(ei, 2 * E, M);
    init_deg_kernel<<<(M + T - 1) / T, T>>>(pDeg, M);
    deg_accum_kernel<<<(E + T - 1) / T, T>>>(pDeg, ei, E, M);
    dinv_kernel<<<(M + T - 1) / T, T>>>(pDeg, M);

    const int gM  = (M + 127) / 128;
    const int w64 = E * 16;    // scatter work items, D=64
    const int w40 = E * 10;
    const int e64 = M * 16;    // epilogue work items
    const int e40 = M * 10;

    // Layer 1
    gemm_scale_kernel<128, 64><<<gM, 128>>>(x, W1, pDeg, pA, pB, M);
    scatter_kernel<64><<<(w64 + T - 1) / T, T>>>(pA, pB, ei, E, M);
    epilogue_kernel<64, true><<<(e64 + T - 1) / T, T>>>(pB, pDeg, b1, pC, M);

    // Layer 2
    gemm_scale_kernel<64, 64><<<gM, 128>>>(pC, W2, pDeg, pA, pB, M);
    scatter_kernel<64><<<(w64 + T - 1) / T, T>>>(pA, pB, ei, E, M);
    epilogue_kernel<64, true><<<(e64 + T - 1) / T, T>>>(pB, pDeg, b2, pA, M);

    // Layer 3
    gemm_scale_kernel<64, 40><<<gM, 128>>>(pA, W3, pDeg, pC, pB, M);
    scatter_kernel<40><<<(w40 + T - 1) / T, T>>>(pC, pB, ei, E, M);
    epilogue_kernel<40, false><<<(e40 + T - 1) / T, T>>>(pB, pDeg, b3, out, M);
}

// round 7
// speedup vs baseline: 1.3009x; 1.3009x over previous
#include <cuda_runtime.h>
#include <cuda_bf16.h>
#include <cstdint>

// ---------------------------------------------------------------------------
// GCN (3-layer) on GB300 — CSR gather-reduce version.
//   pre:  deg histogram -> exclusive scan -> CSR fill (row ids per col)
//   per layer: xw = (H @ W) * dinv[row]        (f32x2 packed-FMA GEMM)
//              out[c] = relu( (xw[c] + sum_nbr xw[nbr]) * dinv[c] + b )
// Edge index dtype (int32 vs int64) auto-detected on device.
// ---------------------------------------------------------------------------

#define N_MAX 100000
#define E_MAX 1600000
#define D_H   64

static __device__ __align__(256) float g_bufA[(size_t)N_MAX * D_H];   // xw
static __device__ __align__(256) float g_bufB[(size_t)N_MAX * D_H];   // h1
static __device__ __align__(256) float g_bufC[(size_t)N_MAX * D_H];   // h2
static __device__ __align__(256) float g_dinv[N_MAX];
static __device__ int g_degi[N_MAX];
static __device__ int g_cursor[N_MAX];
static __device__ int g_ptr[N_MAX + 1];
static __device__ int g_bsum[1024];
static __device__ int g_erow[E_MAX];
static __device__ int g_mode;  // 0 = int64 indices, 1 = int32 indices

// ---------------- dtype detection ----------------
__global__ void detect_mode_kernel(const void* ei, int cnt64, int n) {
    __shared__ int bad;
    if (threadIdx.x == 0) bad = 0;
    __syncthreads();
    const long long* p = (const long long*)ei;
    int cnt = min(cnt64, 1024);
    for (int i = threadIdx.x; i < cnt; i += blockDim.x) {
        unsigned long long v = (unsigned long long)p[i];
        if (v >= (unsigned long long)n) atomicOr(&bad, 1);
    }
    __syncthreads();
    if (threadIdx.x == 0) g_mode = bad ? 1 : 0;
}

__device__ __forceinline__ int edge_idx(const void* ei, long long pos, int mode) {
    return mode ? ((const int*)ei)[pos] : (int)((const long long*)ei)[pos];
}

// ---------------- CSR build ----------------

__global__ void zero_kernel(int* degi, int* cursor, int n) {
    int i = blockIdx.x * blockDim.x + threadIdx.x;
    if (i < n) { degi[i] = 0; cursor[i] = 0; }
}

__global__ void deg_count_kernel(int* degi, const void* ei, int E, int n) {
    int e = blockIdx.x * blockDim.x + threadIdx.x;
    if (e < E) {
        int mode = g_mode;
        unsigned c = (unsigned)edge_idx(ei, (long long)E + e, mode);  // col
        if (c < (unsigned)n) atomicAdd(&degi[c], 1);
    }
}

__global__ void scanA_kernel(const int* degi, int* ptr, int* bsum, int n) {
    __shared__ int s[256];
    int i = blockIdx.x * 256 + threadIdx.x;
    int v = (i < n) ? degi[i] : 0;
    s[threadIdx.x] = v;
    __syncthreads();
    for (int off = 1; off < 256; off <<= 1) {
        int t = (threadIdx.x >= off) ? s[threadIdx.x - off] : 0;
        __syncthreads();
        s[threadIdx.x] += t;
        __syncthreads();
    }
    if (i < n) ptr[i] = s[threadIdx.x] - v;   // exclusive within block
    if (threadIdx.x == 255) bsum[blockIdx.x] = s[255];
}

__global__ void scanB_kernel(int* bsum, int nb) {
    __shared__ int s[1024];
    int v = (threadIdx.x < nb) ? bsum[threadIdx.x] : 0;
    s[threadIdx.x] = v;
    __syncthreads();
    for (int off = 1; off < 1024; off <<= 1) {
        int t = (threadIdx.x >= off) ? s[threadIdx.x - off] : 0;
        __syncthreads();
        s[threadIdx.x] += t;
        __syncthreads();
    }
    if (threadIdx.x < nb) bsum[threadIdx.x] = s[threadIdx.x] - v;  // exclusive
}

__global__ void scanC_kernel(int* ptr, const int* bsum, int n, int E) {
    int i = blockIdx.x * 256 + threadIdx.x;
    if (i < n) ptr[i] += bsum[blockIdx.x];
    if (i == 0) ptr[n] = E;
}

__global__ void dinv_kernel(float* dinv, const int* degi, int n) {
    int i = blockIdx.x * blockDim.x + threadIdx.x;
    if (i < n) dinv[i] = rsqrtf(1.0f + (float)degi[i]);  // +1 self loop
}

__global__ void fill_kernel(const void* ei, const int* ptr, int* cursor,
                            int* erow, int E, int n) {
    int e = blockIdx.x * blockDim.x + threadIdx.x;
    if (e < E) {
        int mode = g_mode;
        unsigned r = (unsigned)edge_idx(ei, e, mode);
        unsigned c = (unsigned)edge_idx(ei, (long long)E + e, mode);
        if (r >= (unsigned)n || c >= (unsigned)n) return;
        int pos = ptr[c] + atomicAdd(&cursor[c], 1);
        erow[pos] = (int)r;
    }
}

// ---------------- GEMM + dinv[row] scale (f32x2 packed FMA) ----------------

__device__ __forceinline__ void fma2(unsigned long long& d,
                                     unsigned long long a,
                                     unsigned long long b) {
    asm("fma.rn.f32x2 %0, %1, %2, %3;" : "=l"(d) : "l"(a), "l"(b), "l"(d));
}

template <int DIN, int DOUT>
__global__ void gemm_scale_kernel(const float* __restrict__ X,
                                  const float* __restrict__ W,
                                  const float* __restrict__ dinv,
                                  float* __restrict__ xw,
                                  int M) {
    constexpr int KT = 16;
    __shared__ __align__(16) float Ws[DIN * DOUT];
    __shared__ float Xs[128 * (KT + 1)];

    const int tid = threadIdx.x;           // 0..127
    const int row0 = blockIdx.x * 128;
    const int row = row0 + tid;

    for (int i = tid; i < DIN * DOUT; i += 128) Ws[i] = W[i];

    unsigned long long a2[DOUT / 2];
#pragma unroll
    for (int j = 0; j < DOUT / 2; j++) a2[j] = 0ull;

    for (int k0 = 0; k0 < DIN; k0 += KT) {
        __syncthreads();
        for (int f = tid; f < 128 * (KT / 4); f += 128) {
            int r = f >> 2;
            int c = (f & 3) * 4;
            int gr = row0 + r;
            float4 v = make_float4(0.f, 0.f, 0.f, 0.f);
            if (gr < M) v = *(const float4*)&X[(size_t)gr * DIN + k0 + c];
            float* dst = &Xs[r * (KT + 1) + c];
            dst[0] = v.x; dst[1] = v.y; dst[2] = v.z; dst[3] = v.w;
        }
        __syncthreads();
#pragma unroll
        for (int k = 0; k < KT; k++) {
            float xv = Xs[tid * (KT + 1) + k];
            unsigned long long xv2;
            asm("mov.b64 %0, {%1, %2};" : "=l"(xv2) : "f"(xv), "f"(xv));
            const float* wrow = &Ws[(k0 + k) * DOUT];
#pragma unroll
            for (int j = 0; j < DOUT; j += 4) {
                ulonglong2 ww = *(const ulonglong2*)&wrow[j];
                fma2(a2[j / 2],     xv2, ww.x);
                fma2(a2[j / 2 + 1], xv2, ww.y);
            }
        }
    }

    if (row < M) {
        float s = dinv[row];
#pragma unroll
        for (int j = 0; j < DOUT; j += 4) {
            float x0, x1, x2, x3;
            asm("mov.b64 {%0, %1}, %2;" : "=f"(x0), "=f"(x1) : "l"(a2[j / 2]));
            asm("mov.b64 {%0, %1}, %2;" : "=f"(x2), "=f"(x3) : "l"(a2[j / 2 + 1]));
            float4 v = make_float4(x0 * s, x1 * s, x2 * s, x3 * s);
            *(float4*)&xw[(size_t)row * DOUT + j] = v;
        }
    }
}

// ---------------- gather-reduce + fused epilogue ----------------
// NPB nodes per block, D threads per node; lane = feature -> coalesced rows.

template <int D, int NPB, bool RELU>
__global__ void gather_kernel(const float* __restrict__ xw,
                              const int* __restrict__ ptr,
                              const int* __restrict__ erow,
                              const float* __restrict__ dinv,
                              const float* __restrict__ b,
                              float* __restrict__ out,
                              int n) {
    int tid = threadIdx.x;
    int nl = tid / D;
    int feat = tid - nl * D;
    int node = blockIdx.x * NPB + nl;
    if (node >= n) return;

    int start = __ldg(&ptr[node]);
    int end   = __ldg(&ptr[node + 1]);

    float acc = __ldg(&xw[(size_t)node * D + feat]);   // self loop (pre-scaled)

    int j = start;
    for (; j + 4 <= end; j += 4) {
        int n0 = __ldg(&erow[j]);
        int n1 = __ldg(&erow[j + 1]);
        int n2 = __ldg(&erow[j + 2]);
        int n3 = __ldg(&erow[j + 3]);
        float v0 = __ldg(&xw[(size_t)n0 * D + feat]);
        float v1 = __ldg(&xw[(size_t)n1 * D + feat]);
        float v2 = __ldg(&xw[(size_t)n2 * D + feat]);
        float v3 = __ldg(&xw[(size_t)n3 * D + feat]);
        acc += v0 + v1 + v2 + v3;
    }
    for (; j < end; j++)
        acc += __ldg(&xw[(size_t)__ldg(&erow[j]) * D + feat]);

    float o = acc * __ldg(&dinv[node]) + __ldg(&b[feat]);
    if (RELU) o = fmaxf(o, 0.f);
    out[(size_t)node * D + feat] = o;
}

// ---------------- launch ----------------

extern "C" void kernel_launch(void* const* d_in, const int* in_sizes, int n_in,
                              void* d_out, int out_size) {
    int i_x = -1, i_ei = -1, i_w1 = -1, i_w2 = -1, i_w3 = -1;
    int i_b1 = -1, i_b2 = -1, i_b3 = -1;
    for (int i = 0; i < n_in; i++) {
        int s = in_sizes[i];
        if      (s == 12800000) i_x  = i;
        else if (s == 3200000)  i_ei = i;
        else if (s == 8192)     i_w1 = i;
        else if (s == 4096)     i_w2 = i;
        else if (s == 2560)     i_w3 = i;
        else if (s == 40)       i_b3 = i;
        else if (s == 64)       { if (i_b1 < 0) i_b1 = i; else i_b2 = i; }
    }
    if (i_x < 0 || i_ei < 0 || i_w1 < 0 || i_b1 < 0 || i_w2 < 0 ||
        i_b2 < 0 || i_w3 < 0 || i_b3 < 0) {
        i_x = 0; i_ei = 1; i_w1 = 2; i_b1 = 3; i_w2 = 4; i_b2 = 5; i_w3 = 6; i_b3 = 7;
    }

    const float* x  = (const float*)d_in[i_x];
    const void*  ei = d_in[i_ei];
    const float* W1 = (const float*)d_in[i_w1];
    const float* b1 = (const float*)d_in[i_b1];
    const float* W2 = (const float*)d_in[i_w2];
    const float* b2 = (const float*)d_in[i_b2];
    const float* W3 = (const float*)d_in[i_w3];
    const float* b3 = (const float*)d_in[i_b3];

    const int M = in_sizes[i_x] / 128;     // 100000
    const int E = in_sizes[i_ei] / 2;      // 1600000
    float* out = (float*)d_out;

    float *pA, *pB, *pC, *pDinv;
    int *pDeg, *pCur, *pPtr, *pBsum, *pErow;
    cudaGetSymbolAddress((void**)&pA, g_bufA);
    cudaGetSymbolAddress((void**)&pB, g_bufB);
    cudaGetSymbolAddress((void**)&pC, g_bufC);
    cudaGetSymbolAddress((void**)&pDinv, g_dinv);
    cudaGetSymbolAddress((void**)&pDeg, g_degi);
    cudaGetSymbolAddress((void**)&pCur, g_cursor);
    cudaGetSymbolAddress((void**)&pPtr, g_ptr);
    cudaGetSymbolAddress((void**)&pBsum, g_bsum);
    cudaGetSymbolAddress((void**)&pErow, g_erow);

    const int T = 256;
    const int nbN = (M + 255) / 256;       // 391 blocks over nodes
    const int nbE = (E + T - 1) / T;

    // --- CSR build + dinv ---
    detect_mode_kernel<<<1, 256>>>(ei, 2 * E, M);
    zero_kernel<<<nbN, T>>>(pDeg, pCur, M);
    deg_count_kernel<<<nbE, T>>>(pDeg, ei, E, M);
    scanA_kernel<<<nbN, 256>>>(pDeg, pPtr, pBsum, M);
    scanB_kernel<<<1, 1024>>>(pBsum, nbN);
    scanC_kernel<<<nbN, 256>>>(pPtr, pBsum, M, E);
    dinv_kernel<<<nbN, T>>>(pDinv, pDeg, M);
    fill_kernel<<<nbE, T>>>(ei, pPtr, pCur, pErow, E, M);

    const int gM  = (M + 127) / 128;
    const int g64 = (M + 3) / 4;           // 4 nodes/block, 256 thr
    const int g40 = (M + 7) / 8;           // 8 nodes/block, 320 thr

    // Layer 1
    gemm_scale_kernel<128, 64><<<gM, 128>>>(x, W1, pDinv, pA, M);
    gather_kernel<64, 4, true><<<g64, 256>>>(pA, pPtr, pErow, pDinv, b1, pB, M);

    // Layer 2
    gemm_scale_kernel<64, 64><<<gM, 128>>>(pB, W2, pDinv, pA, M);
    gather_kernel<64, 4, true><<<g64, 256>>>(pA, pPtr, pErow, pDinv, b2, pC, M);

    // Layer 3
    gemm_scale_kernel<64, 40><<<gM, 128>>>(pC, W3, pDinv, pA, M);
    gather_kernel<40, 8, false><<<g40, 320>>>(pA, pPtr, pErow, pDinv, b3, out, M);
}

// round 8
// speedup vs baseline: 1.5444x; 1.1871x over previous
#include <cuda_runtime.h>
#include <cuda_fp16.h>
#include <cstdint>

// ---------------------------------------------------------------------------
// GCN (3-layer) on GB300 — CSR gather + half-precision xw intermediate.
//   xw = (H @ W) * dinv[row]  stored as fp16 (half2)   [f32x2 packed-FMA GEMM]
//   out[c] = relu( (xw[c] + sum_nbr xw[nbr]) * dinv[c] + b )   fp32 accumulate
// ---------------------------------------------------------------------------

#define N_MAX 100000
#define E_MAX 1600000
#define D_H   64

static __device__ __align__(256) float g_bufA[(size_t)N_MAX * D_H];   // xw (half)
static __device__ __align__(256) float g_bufB[(size_t)N_MAX * D_H];   // h1
static __device__ __align__(256) float g_bufC[(size_t)N_MAX * D_H];   // h2
static __device__ __align__(256) float g_dinv[N_MAX];
static __device__ int g_degi[N_MAX];
static __device__ int g_cursor[N_MAX];
static __device__ int g_ptr[N_MAX + 1];
static __device__ int g_bsum[1024];
static __device__ int g_erow[E_MAX];
static __device__ int g_mode;  // 0 = int64 indices, 1 = int32 indices

// ---------------- dtype detection ----------------
__global__ void detect_mode_kernel(const void* ei, int cnt64, int n) {
    __shared__ int bad;
    if (threadIdx.x == 0) bad = 0;
    __syncthreads();
    const long long* p = (const long long*)ei;
    int cnt = min(cnt64, 1024);
    for (int i = threadIdx.x; i < cnt; i += blockDim.x) {
        unsigned long long v = (unsigned long long)p[i];
        if (v >= (unsigned long long)n) atomicOr(&bad, 1);
    }
    __syncthreads();
    if (threadIdx.x == 0) g_mode = bad ? 1 : 0;
}

__device__ __forceinline__ int edge_idx(const void* ei, long long pos, int mode) {
    return mode ? ((const int*)ei)[pos] : (int)((const long long*)ei)[pos];
}

// ---------------- CSR build ----------------

__global__ void deg_count_kernel(int* degi, const void* ei, int E, int n) {
    int e = blockIdx.x * blockDim.x + threadIdx.x;
    if (e < E) {
        int mode = g_mode;
        unsigned c = (unsigned)edge_idx(ei, (long long)E + e, mode);  // col
        if (c < (unsigned)n) atomicAdd(&degi[c], 1);
    }
}

__global__ void scanA_kernel(const int* degi, int* ptr, int* bsum, int n) {
    __shared__ int s[256];
    int i = blockIdx.x * 256 + threadIdx.x;
    int v = (i < n) ? degi[i] : 0;
    s[threadIdx.x] = v;
    __syncthreads();
    for (int off = 1; off < 256; off <<= 1) {
        int t = (threadIdx.x >= off) ? s[threadIdx.x - off] : 0;
        __syncthreads();
        s[threadIdx.x] += t;
        __syncthreads();
    }
    if (i < n) ptr[i] = s[threadIdx.x] - v;   // exclusive within block
    if (threadIdx.x == 255) bsum[blockIdx.x] = s[255];
}

__global__ void scanB_kernel(int* bsum, int nb) {
    __shared__ int s[1024];
    int v = (threadIdx.x < nb) ? bsum[threadIdx.x] : 0;
    s[threadIdx.x] = v;
    __syncthreads();
    for (int off = 1; off < 1024; off <<= 1) {
        int t = (threadIdx.x >= off) ? s[threadIdx.x - off] : 0;
        __syncthreads();
        s[threadIdx.x] += t;
        __syncthreads();
    }
    if (threadIdx.x < nb) bsum[threadIdx.x] = s[threadIdx.x] - v;  // exclusive
}

__global__ void scanC_kernel(int* ptr, const int* bsum, int n, int E) {
    int i = blockIdx.x * 256 + threadIdx.x;
    if (i < n) ptr[i] += bsum[blockIdx.x];
    if (i == 0) ptr[n] = E;
}

__global__ void dinv_kernel(float* dinv, const int* degi, int n) {
    int i = blockIdx.x * blockDim.x + threadIdx.x;
    if (i < n) dinv[i] = rsqrtf(1.0f + (float)degi[i]);  // +1 self loop
}

__global__ void fill_kernel(const void* ei, const int* ptr, int* cursor,
                            int* erow, int E, int n) {
    int e = blockIdx.x * blockDim.x + threadIdx.x;
    if (e < E) {
        int mode = g_mode;
        unsigned r = (unsigned)edge_idx(ei, e, mode);
        unsigned c = (unsigned)edge_idx(ei, (long long)E + e, mode);
        if (r >= (unsigned)n || c >= (unsigned)n) return;
        int pos = ptr[c] + atomicAdd(&cursor[c], 1);
        erow[pos] = (int)r;
    }
}

// ---------------- GEMM + dinv[row] scale -> half2 (f32x2 packed FMA) --------

__device__ __forceinline__ void fma2(unsigned long long& d,
                                     unsigned long long a,
                                     unsigned long long b) {
    asm("fma.rn.f32x2 %0, %1, %2, %3;" : "=l"(d) : "l"(a), "l"(b), "l"(d));
}

template <int DIN, int DOUT>
__global__ void gemm_scale_kernel(const float* __restrict__ X,
                                  const float* __restrict__ W,
                                  const float* __restrict__ dinv,
                                  __half2* __restrict__ xwh,
                                  int M) {
    constexpr int KT = 16;
    __shared__ __align__(16) float Ws[DIN * DOUT];
    __shared__ float Xs[128 * (KT + 1)];

    const int tid = threadIdx.x;           // 0..127
    const int row0 = blockIdx.x * 128;
    const int row = row0 + tid;

    for (int i = tid; i < DIN * DOUT; i += 128) Ws[i] = W[i];

    unsigned long long a2[DOUT / 2];
#pragma unroll
    for (int j = 0; j < DOUT / 2; j++) a2[j] = 0ull;

    for (int k0 = 0; k0 < DIN; k0 += KT) {
        __syncthreads();
        for (int f = tid; f < 128 * (KT / 4); f += 128) {
            int r = f >> 2;
            int c = (f & 3) * 4;
            int gr = row0 + r;
            float4 v = make_float4(0.f, 0.f, 0.f, 0.f);
            if (gr < M) v = *(const float4*)&X[(size_t)gr * DIN + k0 + c];
            float* dst = &Xs[r * (KT + 1) + c];
            dst[0] = v.x; dst[1] = v.y; dst[2] = v.z; dst[3] = v.w;
        }
        __syncthreads();
#pragma unroll
        for (int k = 0; k < KT; k++) {
            float xv = Xs[tid * (KT + 1) + k];
            unsigned long long xv2;
            asm("mov.b64 %0, {%1, %2};" : "=l"(xv2) : "f"(xv), "f"(xv));
            const float* wrow = &Ws[(k0 + k) * DOUT];
#pragma unroll
            for (int j = 0; j < DOUT; j += 4) {
                ulonglong2 ww = *(const ulonglong2*)&wrow[j];
                fma2(a2[j / 2],     xv2, ww.x);
                fma2(a2[j / 2 + 1], xv2, ww.y);
            }
        }
    }

    if (row < M) {
        float s = dinv[row];
        __half2* dst = xwh + (size_t)row * (DOUT / 2);
#pragma unroll
        for (int j = 0; j < DOUT; j += 4) {
            float x0, x1, x2, x3;
            asm("mov.b64 {%0, %1}, %2;" : "=f"(x0), "=f"(x1) : "l"(a2[j / 2]));
            asm("mov.b64 {%0, %1}, %2;" : "=f"(x2), "=f"(x3) : "l"(a2[j / 2 + 1]));
            uint2 pack;
            __half2 h0 = __floats2half2_rn(x0 * s, x1 * s);
            __half2 h1 = __floats2half2_rn(x2 * s, x3 * s);
            pack.x = *(unsigned*)&h0;
            pack.y = *(unsigned*)&h1;
            *(uint2*)&dst[j / 2] = pack;
        }
    }
}

// ---------------- gather-reduce + fused epilogue (D = 64: warp per node) ----

template <bool RELU>
__global__ void gather64_kernel(const __half2* __restrict__ xwh,
                                const int* __restrict__ ptr,
                                const int* __restrict__ erow,
                                const float* __restrict__ dinv,
                                const float* __restrict__ b,
                                float* __restrict__ out,
                                int n) {
    int lane = threadIdx.x & 31;            // feature pair 0..31
    int node = blockIdx.x * 8 + (threadIdx.x >> 5);
    if (node >= n) return;

    int start = __ldg(&ptr[node]);
    int end   = __ldg(&ptr[node + 1]);

    float2 acc = __half22float2(__ldg(&xwh[(size_t)node * 32 + lane]));  // self

    int cnt = end - start;
    int j = start, j8 = start + (cnt & ~7);
    for (; j < j8; j += 8) {
        int ids[8];
#pragma unroll
        for (int k = 0; k < 8; k++) ids[k] = __ldg(&erow[j + k]);
#pragma unroll
        for (int k = 0; k < 8; k++) {
            float2 f = __half22float2(__ldg(&xwh[(size_t)ids[k] * 32 + lane]));
            acc.x += f.x; acc.y += f.y;
        }
    }
    for (; j < end; j++) {
        float2 f = __half22float2(__ldg(&xwh[(size_t)__ldg(&erow[j]) * 32 + lane]));
        acc.x += f.x; acc.y += f.y;
    }

    float s = __ldg(&dinv[node]);
    float2 bb = __ldg((const float2*)b + lane);
    float2 o = make_float2(acc.x * s + bb.x, acc.y * s + bb.y);
    if (RELU) { o.x = fmaxf(o.x, 0.f); o.y = fmaxf(o.y, 0.f); }
    ((float2*)out)[(size_t)node * 32 + lane] = o;
}

// ---------------- gather-reduce, D = 40: 20 threads per node ----------------

__global__ void gather40_kernel(const __half2* __restrict__ xwh,
                                const int* __restrict__ ptr,
                                const int* __restrict__ erow,
                                const float* __restrict__ dinv,
                                const float* __restrict__ b,
                                float* __restrict__ out,
                                int n) {
    int tid = threadIdx.x;
    if (tid >= 240) return;                  // 12 nodes * 20 threads
    int nl = tid / 20;
    int lane = tid - nl * 20;                // feature pair 0..19
    int node = blockIdx.x * 12 + nl;
    if (node >= n) return;

    int start = __ldg(&ptr[node]);
    int end   = __ldg(&ptr[node + 1]);

    float2 acc = __half22float2(__ldg(&xwh[(size_t)node * 20 + lane]));  // self

    int cnt = end - start;
    int j = start, j8 = start + (cnt & ~7);
    for (; j < j8; j += 8) {
        int ids[8];
#pragma unroll
        for (int k = 0; k < 8; k++) ids[k] = __ldg(&erow[j + k]);
#pragma unroll
        for (int k = 0; k < 8; k++) {
            float2 f = __half22float2(__ldg(&xwh[(size_t)ids[k] * 20 + lane]));
            acc.x += f.x; acc.y += f.y;
        }
    }
    for (; j < end; j++) {
        float2 f = __half22float2(__ldg(&xwh[(size_t)__ldg(&erow[j]) * 20 + lane]));
        acc.x += f.x; acc.y += f.y;
    }

    float s = __ldg(&dinv[node]);
    float2 bb = __ldg((const float2*)b + lane);
    float2 o = make_float2(acc.x * s + bb.x, acc.y * s + bb.y);
    ((float2*)out)[(size_t)node * 20 + lane] = o;
}

// ---------------- launch ----------------

extern "C" void kernel_launch(void* const* d_in, const int* in_sizes, int n_in,
                              void* d_out, int out_size) {
    int i_x = -1, i_ei = -1, i_w1 = -1, i_w2 = -1, i_w3 = -1;
    int i_b1 = -1, i_b2 = -1, i_b3 = -1;
    for (int i = 0; i < n_in; i++) {
        int s = in_sizes[i];
        if      (s == 12800000) i_x  = i;
        else if (s == 3200000)  i_ei = i;
        else if (s == 8192)     i_w1 = i;
        else if (s == 4096)     i_w2 = i;
        else if (s == 2560)     i_w3 = i;
        else if (s == 40)       i_b3 = i;
        else if (s == 64)       { if (i_b1 < 0) i_b1 = i; else i_b2 = i; }
    }
    if (i_x < 0 || i_ei < 0 || i_w1 < 0 || i_b1 < 0 || i_w2 < 0 ||
        i_b2 < 0 || i_w3 < 0 || i_b3 < 0) {
        i_x = 0; i_ei = 1; i_w1 = 2; i_b1 = 3; i_w2 = 4; i_b2 = 5; i_w3 = 6; i_b3 = 7;
    }

    const float* x  = (const float*)d_in[i_x];
    const void*  ei = d_in[i_ei];
    const float* W1 = (const float*)d_in[i_w1];
    const float* b1 = (const float*)d_in[i_b1];
    const float* W2 = (const float*)d_in[i_w2];
    const float* b2 = (const float*)d_in[i_b2];
    const float* W3 = (const float*)d_in[i_w3];
    const float* b3 = (const float*)d_in[i_b3];

    const int M = in_sizes[i_x] / 128;     // 100000
    const int E = in_sizes[i_ei] / 2;      // 1600000
    float* out = (float*)d_out;

    float *pA, *pB, *pC, *pDinv;
    int *pDeg, *pCur, *pPtr, *pBsum, *pErow;
    cudaGetSymbolAddress((void**)&pA, g_bufA);
    cudaGetSymbolAddress((void**)&pB, g_bufB);
    cudaGetSymbolAddress((void**)&pC, g_bufC);
    cudaGetSymbolAddress((void**)&pDinv, g_dinv);
    cudaGetSymbolAddress((void**)&pDeg, g_degi);
    cudaGetSymbolAddress((void**)&pCur, g_cursor);
    cudaGetSymbolAddress((void**)&pPtr, g_ptr);
    cudaGetSymbolAddress((void**)&pBsum, g_bsum);
    cudaGetSymbolAddress((void**)&pErow, g_erow);
    __half2* pAh = (__half2*)pA;

    const int T = 256;
    const int nbN = (M + 255) / 256;
    const int nbE = (E + T - 1) / T;

    // --- CSR build prefix (stream 0) ---
    detect_mode_kernel<<<1, 256>>>(ei, 2 * E, M);
    cudaMemsetAsync(pDeg, 0, (size_t)M * sizeof(int), 0);
    cudaMemsetAsync(pCur, 0, (size_t)M * sizeof(int), 0);
    deg_count_kernel<<<nbE, T>>>(pDeg, ei, E, M);
    scanA_kernel<<<nbN, 256>>>(pDeg, pPtr, pBsum, M);
    scanB_kernel<<<1, 1024>>>(pBsum, nbN);
    scanC_kernel<<<nbN, 256>>>(pPtr, pBsum, M, E);
    dinv_kernel<<<nbN, T>>>(pDinv, pDeg, M);

    // --- fork: fill on side stream, GEMM1 on stream 0, join before gather1 ---
    cudaStream_t s2;
    cudaEvent_t evD, evF;
    bool forked = (cudaStreamCreateWithFlags(&s2, cudaStreamNonBlocking) == cudaSuccess) &&
                  (cudaEventCreateWithFlags(&evD, cudaEventDisableTiming) == cudaSuccess) &&
                  (cudaEventCreateWithFlags(&evF, cudaEventDisableTiming) == cudaSuccess);

    const int gM  = (M + 127) / 128;
    const int g64 = (M + 7) / 8;
    const int g40 = (M + 11) / 12;

    if (forked) {
        cudaEventRecord(evD, 0);
        cudaStreamWaitEvent(s2, evD, 0);
        fill_kernel<<<nbE, T, 0, s2>>>(ei, pPtr, pCur, pErow, E, M);
        cudaEventRecord(evF, s2);
        gemm_scale_kernel<128, 64><<<gM, 128>>>(x, W1, pDinv, pAh, M);
        cudaStreamWaitEvent(0, evF, 0);
    } else {
        fill_kernel<<<nbE, T>>>(ei, pPtr, pCur, pErow, E, M);
        gemm_scale_kernel<128, 64><<<gM, 128>>>(x, W1, pDinv, pAh, M);
    }

    // Layer 1 aggregation
    gather64_kernel<true><<<g64, 256>>>(pAh, pPtr, pErow, pDinv, b1, pB, M);

    // Layer 2
    gemm_scale_kernel<64, 64><<<gM, 128>>>(pB, W2, pDinv, pAh, M);
    gather64_kernel<true><<<g64, 256>>>(pAh, pPtr, pErow, pDinv, b2, pC, M);

    // Layer 3
    gemm_scale_kernel<64, 40><<<gM, 128>>>(pC, W3, pDinv, pAh, M);
    gather40_kernel<<<g40, 256>>>(pAh, pPtr, pErow, pDinv, b3, out, M);
}

// round 9
// speedup vs baseline: 1.6785x; 1.0868x over previous
#include <cuda_runtime.h>
#include <cuda_fp16.h>
#include <cstdint>

// ---------------------------------------------------------------------------
// GCN (3-layer) on GB300 — CSR gather, fp16 intermediates everywhere.
//   xw = (H @ W) * dinv[row]  stored fp16, row stride 32 half2 (128B) all layers
//   h  = relu( (xw[c] + sum_nbr xw[nbr]) * dinv[c] + b )  stored fp16
//   final layer output fp32.
// ---------------------------------------------------------------------------

#define N_MAX 100000
#define E_MAX 1600000

static __device__ __align__(256) __half2 g_xw[(size_t)N_MAX * 32];   // xw, stride 32
static __device__ __align__(256) __half2 g_h[(size_t)N_MAX * 32];    // h,  stride 32
static __device__ __align__(256) float g_dinv[N_MAX];
static __device__ int g_degi[N_MAX];
static __device__ int g_cursor[N_MAX];
static __device__ int g_ptr[N_MAX + 1];
static __device__ int g_bsum[1024];
static __device__ int g_erow[E_MAX];
static __device__ int g_mode;  // 0 = int64 indices, 1 = int32 indices

// ---------------- dtype detection ----------------
__global__ void detect_mode_kernel(const void* ei, int cnt64, int n) {
    __shared__ int bad;
    if (threadIdx.x == 0) bad = 0;
    __syncthreads();
    const long long* p = (const long long*)ei;
    int cnt = min(cnt64, 1024);
    for (int i = threadIdx.x; i < cnt; i += blockDim.x) {
        unsigned long long v = (unsigned long long)p[i];
        if (v >= (unsigned long long)n) atomicOr(&bad, 1);
    }
    __syncthreads();
    if (threadIdx.x == 0) g_mode = bad ? 1 : 0;
}

__device__ __forceinline__ int edge_idx(const void* ei, long long pos, int mode) {
    return mode ? ((const int*)ei)[pos] : (int)((const long long*)ei)[pos];
}

// ---------------- CSR build ----------------

__global__ void deg_count_kernel(int* degi, const void* ei, int E, int n) {
    int e = blockIdx.x * blockDim.x + threadIdx.x;
    if (e < E) {
        int mode = g_mode;
        unsigned c = (unsigned)edge_idx(ei, (long long)E + e, mode);  // col
        if (c < (unsigned)n) atomicAdd(&degi[c], 1);
    }
}

__global__ void scanA_kernel(const int* degi, int* ptr, int* bsum, int n) {
    __shared__ int s[256];
    int i = blockIdx.x * 256 + threadIdx.x;
    int v = (i < n) ? degi[i] : 0;
    s[threadIdx.x] = v;
    __syncthreads();
    for (int off = 1; off < 256; off <<= 1) {
        int t = (threadIdx.x >= off) ? s[threadIdx.x - off] : 0;
        __syncthreads();
        s[threadIdx.x] += t;
        __syncthreads();
    }
    if (i < n) ptr[i] = s[threadIdx.x] - v;   // exclusive within block
    if (threadIdx.x == 255) bsum[blockIdx.x] = s[255];
}

__global__ void scanB_kernel(int* bsum, int nb) {
    __shared__ int s[1024];
    int v = (threadIdx.x < nb) ? bsum[threadIdx.x] : 0;
    s[threadIdx.x] = v;
    __syncthreads();
    for (int off = 1; off < 1024; off <<= 1) {
        int t = (threadIdx.x >= off) ? s[threadIdx.x - off] : 0;
        __syncthreads();
        s[threadIdx.x] += t;
        __syncthreads();
    }
    if (threadIdx.x < nb) bsum[threadIdx.x] = s[threadIdx.x] - v;  // exclusive
}

// scanC + dinv + cursor init, fused (all node-indexed).
__global__ void scanC_fused_kernel(int* ptr, const int* bsum, int* cursor,
                                   float* dinv, const int* degi, int n, int E) {
    int i = blockIdx.x * 256 + threadIdx.x;
    if (i < n) {
        int p = ptr[i] + bsum[blockIdx.x];
        ptr[i] = p;
        cursor[i] = p;                               // fill writes from here
        dinv[i] = rsqrtf(1.0f + (float)degi[i]);     // +1 self loop
    }
    if (i == 0) ptr[n] = E;
}

__global__ void fill_kernel(const void* ei, int* cursor, int* erow, int E, int n) {
    int e = blockIdx.x * blockDim.x + threadIdx.x;
    if (e < E) {
        int mode = g_mode;
        unsigned r = (unsigned)edge_idx(ei, e, mode);
        unsigned c = (unsigned)edge_idx(ei, (long long)E + e, mode);
        if (r >= (unsigned)n || c >= (unsigned)n) return;
        int pos = atomicAdd(&cursor[c], 1);
        erow[pos] = (int)r;
    }
}

// ---------------- GEMM + dinv[row] scale -> half2, stride 32 ----------------
// One thread per output row; X loaded directly (no cross-thread reuse),
// W broadcast from smem; f32x2 packed FMA (SASS FFMA2).

__device__ __forceinline__ void fma2(unsigned long long& d,
                                     unsigned long long a,
                                     unsigned long long b) {
    asm("fma.rn.f32x2 %0, %1, %2, %3;" : "=l"(d) : "l"(a), "l"(b), "l"(d));
}

template <int DIN, int DOUT, bool HALF_IN>
__global__ void gemm_kernel(const void* __restrict__ Xv,
                            const float* __restrict__ W,
                            const float* __restrict__ dinv,
                            __half2* __restrict__ xwh,
                            int M) {
    __shared__ __align__(16) float Ws[DIN * DOUT];
    const int tid = threadIdx.x;           // 0..127
    const int row = blockIdx.x * 128 + tid;

    for (int i = tid; i < DIN * DOUT; i += 128) Ws[i] = W[i];
    __syncthreads();

    unsigned long long a2[DOUT / 2];
#pragma unroll
    for (int j = 0; j < DOUT / 2; j++) a2[j] = 0ull;

    const bool act = (row < M);

#pragma unroll
    for (int k0 = 0; k0 < DIN; k0 += 16) {
        float xr[16];
        if (act) {
            if (HALF_IN) {
                const uint4* src = (const uint4*)((const __half*)Xv + (size_t)row * DIN + k0);
                uint4 u0 = __ldg(src);
                uint4 u1 = __ldg(src + 1);
                const unsigned* uu = &u0.x;
#pragma unroll
                for (int q = 0; q < 4; q++) {
                    float2 f = __half22float2(*(const __half2*)&uu[q]);
                    xr[q * 2] = f.x; xr[q * 2 + 1] = f.y;
                }
                const unsigned* vv = &u1.x;
#pragma unroll
                for (int q = 0; q < 4; q++) {
                    float2 f = __half22float2(*(const __half2*)&vv[q]);
                    xr[8 + q * 2] = f.x; xr[8 + q * 2 + 1] = f.y;
                }
            } else {
                const float4* src = (const float4*)((const float*)Xv + (size_t)row * DIN + k0);
#pragma unroll
                for (int q = 0; q < 4; q++) {
                    float4 v = __ldg(src + q);
                    xr[q * 4] = v.x; xr[q * 4 + 1] = v.y;
                    xr[q * 4 + 2] = v.z; xr[q * 4 + 3] = v.w;
                }
            }
        } else {
#pragma unroll
            for (int q = 0; q < 16; q++) xr[q] = 0.f;
        }
#pragma unroll
        for (int k = 0; k < 16; k++) {
            unsigned long long xv2;
            asm("mov.b64 %0, {%1, %2};" : "=l"(xv2) : "f"(xr[k]), "f"(xr[k]));
            const float* wrow = &Ws[(k0 + k) * DOUT];
#pragma unroll
            for (int j = 0; j < DOUT; j += 4) {
                ulonglong2 ww = *(const ulonglong2*)&wrow[j];
                fma2(a2[j / 2],     xv2, ww.x);
                fma2(a2[j / 2 + 1], xv2, ww.y);
            }
        }
    }

    if (act) {
        float s = dinv[row];
        __half2* dst = xwh + (size_t)row * 32;      // padded stride
#pragma unroll
        for (int p = 0; p < DOUT / 2; p += 2) {
            float x0, x1, x2, x3;
            asm("mov.b64 {%0, %1}, %2;" : "=f"(x0), "=f"(x1) : "l"(a2[p]));
            asm("mov.b64 {%0, %1}, %2;" : "=f"(x2), "=f"(x3) : "l"(a2[p + 1]));
            uint2 pack;
            __half2 h0 = __floats2half2_rn(x0 * s, x1 * s);
            __half2 h1 = __floats2half2_rn(x2 * s, x3 * s);
            pack.x = *(unsigned*)&h0;
            pack.y = *(unsigned*)&h1;
            *(uint2*)&dst[p] = pack;
        }
    }
}

// ---------------- gather-reduce + fused epilogue (warp per node) ------------
// D=64: lanes 0..31 = feature pairs; output fp16 (stride 32 half2).

__global__ void gather64h_kernel(const __half2* __restrict__ xwh,
                                 const int* __restrict__ ptr,
                                 const int* __restrict__ erow,
                                 const float* __restrict__ dinv,
                                 const float* __restrict__ b,
                                 __half2* __restrict__ out,
                                 int n) {
    int lane = threadIdx.x & 31;
    int node = blockIdx.x * 8 + (threadIdx.x >> 5);
    if (node >= n) return;

    int start = __ldg(&ptr[node]);
    int end   = __ldg(&ptr[node + 1]);

    float2 acc = __half22float2(__ldg(&xwh[(size_t)node * 32 + lane]));  // self

    int cnt = end - start;
    int j = start, j8 = start + (cnt & ~7);
    for (; j < j8; j += 8) {
        int ids[8];
#pragma unroll
        for (int k = 0; k < 8; k++) ids[k] = __ldg(&erow[j + k]);
#pragma unroll
        for (int k = 0; k < 8; k++) {
            float2 f = __half22float2(__ldg(&xwh[(size_t)ids[k] * 32 + lane]));
            acc.x += f.x; acc.y += f.y;
        }
    }
    for (; j < end; j++) {
        float2 f = __half22float2(__ldg(&xwh[(size_t)__ldg(&erow[j]) * 32 + lane]));
        acc.x += f.x; acc.y += f.y;
    }

    float s = __ldg(&dinv[node]);
    float2 bb = __ldg((const float2*)b + lane);
    float ox = fmaxf(acc.x * s + bb.x, 0.f);
    float oy = fmaxf(acc.y * s + bb.y, 0.f);
    out[(size_t)node * 32 + lane] = __floats2half2_rn(ox, oy);
}

// D=40 final layer: 20 threads/node, xw stride 32 half2, fp32 output.

__global__ void gather40_kernel(const __half2* __restrict__ xwh,
                                const int* __restrict__ ptr,
                                const int* __restrict__ erow,
                                const float* __restrict__ dinv,
                                const float* __restrict__ b,
                                float* __restrict__ out,
                                int n) {
    int tid = threadIdx.x;
    if (tid >= 240) return;                  // 12 nodes * 20 threads
    int nl = tid / 20;
    int lane = tid - nl * 20;                // feature pair 0..19
    int node = blockIdx.x * 12 + nl;
    if (node >= n) return;

    int start = __ldg(&ptr[node]);
    int end   = __ldg(&ptr[node + 1]);

    float2 acc = __half22float2(__ldg(&xwh[(size_t)node * 32 + lane]));  // self

    int cnt = end - start;
    int j = start, j8 = start + (cnt & ~7);
    for (; j < j8; j += 8) {
        int ids[8];
#pragma unroll
        for (int k = 0; k < 8; k++) ids[k] = __ldg(&erow[j + k]);
#pragma unroll
        for (int k = 0; k < 8; k++) {
            float2 f = __half22float2(__ldg(&xwh[(size_t)ids[k] * 32 + lane]));
            acc.x += f.x; acc.y += f.y;
        }
    }
    for (; j < end; j++) {
        float2 f = __half22float2(__ldg(&xwh[(size_t)__ldg(&erow[j]) * 32 + lane]));
        acc.x += f.x; acc.y += f.y;
    }

    float s = __ldg(&dinv[node]);
    float2 bb = __ldg((const float2*)b + lane);
    float2 o = make_float2(acc.x * s + bb.x, acc.y * s + bb.y);
    ((float2*)out)[(size_t)node * 20 + lane] = o;
}

// ---------------- launch ----------------

extern "C" void kernel_launch(void* const* d_in, const int* in_sizes, int n_in,
                              void* d_out, int out_size) {
    int i_x = -1, i_ei = -1, i_w1 = -1, i_w2 = -1, i_w3 = -1;
    int i_b1 = -1, i_b2 = -1, i_b3 = -1;
    for (int i = 0; i < n_in; i++) {
        int s = in_sizes[i];
        if      (s == 12800000) i_x  = i;
        else if (s == 3200000)  i_ei = i;
        else if (s == 8192)     i_w1 = i;
        else if (s == 4096)     i_w2 = i;
        else if (s == 2560)     i_w3 = i;
        else if (s == 40)       i_b3 = i;
        else if (s == 64)       { if (i_b1 < 0) i_b1 = i; else i_b2 = i; }
    }
    if (i_x < 0 || i_ei < 0 || i_w1 < 0 || i_b1 < 0 || i_w2 < 0 ||
        i_b2 < 0 || i_w3 < 0 || i_b3 < 0) {
        i_x = 0; i_ei = 1; i_w1 = 2; i_b1 = 3; i_w2 = 4; i_b2 = 5; i_w3 = 6; i_b3 = 7;
    }

    const float* x  = (const float*)d_in[i_x];
    const void*  ei = d_in[i_ei];
    const float* W1 = (const float*)d_in[i_w1];
    const float* b1 = (const float*)d_in[i_b1];
    const float* W2 = (const float*)d_in[i_w2];
    const float* b2 = (const float*)d_in[i_b2];
    const float* W3 = (const float*)d_in[i_w3];
    const float* b3 = (const float*)d_in[i_b3];

    const int M = in_sizes[i_x] / 128;     // 100000
    const int E = in_sizes[i_ei] / 2;      // 1600000
    float* out = (float*)d_out;

    __half2 *pXw, *pH;
    float* pDinv;
    int *pDeg, *pCur, *pPtr, *pBsum, *pErow;
    cudaGetSymbolAddress((void**)&pXw, g_xw);
    cudaGetSymbolAddress((void**)&pH, g_h);
    cudaGetSymbolAddress((void**)&pDinv, g_dinv);
    cudaGetSymbolAddress((void**)&pDeg, g_degi);
    cudaGetSymbolAddress((void**)&pCur, g_cursor);
    cudaGetSymbolAddress((void**)&pPtr, g_ptr);
    cudaGetSymbolAddress((void**)&pBsum, g_bsum);
    cudaGetSymbolAddress((void**)&pErow, g_erow);

    const int T = 256;
    const int nbN = (M + 255) / 256;
    const int nbE = (E + T - 1) / T;

    // --- CSR build prefix ---
    detect_mode_kernel<<<1, 256>>>(ei, 2 * E, M);
    cudaMemsetAsync(pDeg, 0, (size_t)M * sizeof(int), 0);
    deg_count_kernel<<<nbE, T>>>(pDeg, ei, E, M);
    scanA_kernel<<<nbN, 256>>>(pDeg, pPtr, pBsum, M);
    scanB_kernel<<<1, 1024>>>(pBsum, nbN);
    scanC_fused_kernel<<<nbN, 256>>>(pPtr, pBsum, pCur, pDinv, pDeg, M, E);

    // --- fork: fill on side stream, GEMM1 on stream 0, join before gather1 ---
    cudaStream_t s2;
    cudaEvent_t evD, evF;
    bool forked = (cudaStreamCreateWithFlags(&s2, cudaStreamNonBlocking) == cudaSuccess) &&
                  (cudaEventCreateWithFlags(&evD, cudaEventDisableTiming) == cudaSuccess) &&
                  (cudaEventCreateWithFlags(&evF, cudaEventDisableTiming) == cudaSuccess);

    const int gM  = (M + 127) / 128;
    const int g64 = (M + 7) / 8;
    const int g40 = (M + 11) / 12;

    if (forked) {
        cudaEventRecord(evD, 0);
        cudaStreamWaitEvent(s2, evD, 0);
        fill_kernel<<<nbE, T, 0, s2>>>(ei, pCur, pErow, E, M);
        cudaEventRecord(evF, s2);
        gemm_kernel<128, 64, false><<<gM, 128>>>(x, W1, pDinv, pXw, M);
        cudaStreamWaitEvent(0, evF, 0);
    } else {
        fill_kernel<<<nbE, T>>>(ei, pCur, pErow, E, M);
        gemm_kernel<128, 64, false><<<gM, 128>>>(x, W1, pDinv, pXw, M);
    }

    // Layer 1 aggregation -> h (fp16)
    gather64h_kernel<<<g64, 256>>>(pXw, pPtr, pErow, pDinv, b1, pH, M);

    // Layer 2
    gemm_kernel<64, 64, true><<<gM, 128>>>(pH, W2, pDinv, pXw, M);
    gather64h_kernel<<<g64, 256>>>(pXw, pPtr, pErow, pDinv, b2, pH, M);

    // Layer 3 (DOUT=40, padded stride 32 half2)
    gemm_kernel<64, 40, true><<<gM, 128>>>(pH, W3, pDinv, pXw, M);
    gather40_kernel<<<g40, 256>>>(pXw, pPtr, pErow, pDinv, b3, out, M);
}